// round 2
// baseline (speedup 1.0000x reference)
#include <cuda_runtime.h>
#include <cuda_bf16.h>
#include <math.h>

// ---------------- problem constants ----------------
#define F_IN  128
#define D1    128
#define N_CLS 64
#define MAXN  50000
#define MAXE  800000

// ---------------- device scratch (no allocations allowed) ----------------
__device__ float g_h1[MAXN * D1];      // x @ W1
__device__ float g_a1[MAXN * D1];      // relu(aggregate(h1) + b1)
__device__ float g_h2[MAXN * N_CLS];   // a1 @ W2
__device__ int   g_deg[MAXN];
__device__ float g_dis[MAXN];
__device__ int   g_rowptr[MAXN + 1];
__device__ int   g_cursor[MAXN];
__device__ int   g_srcs[MAXE];
__device__ float g_norm[MAXE];

// ---------------- degree / dis ----------------
__global__ void k_deg_init(int n) {
    int i = blockIdx.x * blockDim.x + threadIdx.x;
    if (i < n) g_deg[i] = 1;   // self loop
}

__global__ void k_deg_count(const int* __restrict__ dst, int E, int n) {
    int e = blockIdx.x * blockDim.x + threadIdx.x;
    if (e >= E) return;
    int d = dst[e];
    if ((unsigned)d < (unsigned)n) atomicAdd(&g_deg[d], 1);
}

__global__ void k_dis(int n) {
    int i = blockIdx.x * blockDim.x + threadIdx.x;
    if (i < n) g_dis[i] = rsqrtf((float)g_deg[i]);
}

// ---------------- exclusive scan of (deg-1) -> rowptr, cursor ----------------
// single block, 1024 threads, warp-shuffle scan per chunk with running carry
__global__ void k_scan(int n) {
    __shared__ int wsum[32];
    __shared__ int carry_s;
    int tid = threadIdx.x, lane = tid & 31, wid = tid >> 5;
    if (tid == 0) carry_s = 0;
    __syncthreads();
    for (int base = 0; base < n; base += 1024) {
        int i = base + tid;
        int v = (i < n) ? (g_deg[i] - 1) : 0;
        int x = v;
        #pragma unroll
        for (int off = 1; off < 32; off <<= 1) {
            int y = __shfl_up_sync(0xffffffffu, x, off);
            if (lane >= off) x += y;
        }
        if (lane == 31) wsum[wid] = x;
        __syncthreads();
        if (wid == 0) {
            int w = wsum[lane];
            #pragma unroll
            for (int off = 1; off < 32; off <<= 1) {
                int y = __shfl_up_sync(0xffffffffu, w, off);
                if (lane >= off) w += y;
            }
            wsum[lane] = w;
        }
        __syncthreads();
        int prefix = carry_s + (wid ? wsum[wid - 1] : 0);
        int excl = prefix + x - v;
        if (i < n) { g_rowptr[i] = excl; g_cursor[i] = excl; }
        __syncthreads();
        if (tid == 0) carry_s += wsum[31];
        __syncthreads();
    }
    if (threadIdx.x == 0) g_rowptr[n] = carry_s;
}

// ---------------- scatter edges into dst-sorted CSR ----------------
__global__ void k_scatter(const int* __restrict__ src,
                          const int* __restrict__ dst, int E, int n) {
    int e = blockIdx.x * blockDim.x + threadIdx.x;
    if (e >= E) return;
    int s = src[e];
    int d = dst[e];
    if ((unsigned)s >= (unsigned)n || (unsigned)d >= (unsigned)n) return;
    int pos = atomicAdd(&g_cursor[d], 1);
    g_srcs[pos] = s;
    g_norm[pos] = g_dis[s] * g_dis[d];
}

// ---------------- SIMT fp32 GEMM: C[M,TN] = A[M,128] @ B[128,TN] ----------------
// block = 256 threads; per-thread tile 8 rows x 4 cols
template <int TN>
__global__ void __launch_bounds__(256) k_gemm(const float* __restrict__ A,
                                              const float* __restrict__ B,
                                              float* __restrict__ C, int M) {
    constexpr int K = 128;
    constexpr int TCOLS = TN / 4;            // 32 (TN=128) or 16 (TN=64)
    constexpr int TM = (256 / TCOLS) * 8;    // 64 or 128
    extern __shared__ float sm[];
    float* Ws = sm;            // [K][TN]
    float* Xs = sm + K * TN;   // [TM][K]
    int tid = threadIdx.x;
    int blockRow = blockIdx.x * TM;

    // load B (whole weight) into smem
    {
        const float4* Bv = (const float4*)B;
        float4* Wv = (float4*)Ws;
        for (int i = tid; i < K * TN / 4; i += 256) Wv[i] = Bv[i];
    }
    // load A tile
    {
        float4* Xv = (float4*)Xs;
        for (int i = tid; i < TM * K / 4; i += 256) {
            int r = i >> 5;          // K/4 == 32 float4 per row
            int c = i & 31;
            int row = blockRow + r;
            float4 val = make_float4(0.f, 0.f, 0.f, 0.f);
            if (row < M) val = ((const float4*)A)[row * 32 + c];
            Xv[i] = val;
        }
    }
    __syncthreads();

    int tx = tid % TCOLS, ty = tid / TCOLS;
    int r0 = ty * 8;
    float4 acc[8];
    #pragma unroll
    for (int r = 0; r < 8; r++) acc[r] = make_float4(0.f, 0.f, 0.f, 0.f);

    #pragma unroll 8
    for (int k = 0; k < K; k++) {
        float4 b = *(const float4*)&Ws[k * TN + tx * 4];
        #pragma unroll
        for (int r = 0; r < 8; r++) {
            float a = Xs[(r0 + r) * K + k];
            acc[r].x += a * b.x;
            acc[r].y += a * b.y;
            acc[r].z += a * b.z;
            acc[r].w += a * b.w;
        }
    }
    #pragma unroll
    for (int r = 0; r < 8; r++) {
        int row = blockRow + r0 + r;
        if (row < M) ((float4*)C)[row * (TN / 4) + tx] = acc[r];
    }
}

// ---------------- aggregation: one warp per node, 128 features ----------------
template <bool RELU>
__global__ void k_agg128(const float* __restrict__ h,
                         const float* __restrict__ bias,
                         float* __restrict__ out, int n) {
    int gwarp = (blockIdx.x * blockDim.x + threadIdx.x) >> 5;
    if (gwarp >= n) return;
    int lane = threadIdx.x & 31;
    const float4* hv = (const float4*)h;
    float d = g_dis[gwarp];
    float4 v = hv[gwarp * 32 + lane];
    float sn = d * d;                           // self-loop norm
    float4 acc = make_float4(sn * v.x, sn * v.y, sn * v.z, sn * v.w);
    int e = g_rowptr[gwarp], e1 = g_rowptr[gwarp + 1];
    for (; e + 4 <= e1; e += 4) {
        int s0 = g_srcs[e + 0], s1 = g_srcs[e + 1], s2 = g_srcs[e + 2], s3 = g_srcs[e + 3];
        float n0 = g_norm[e + 0], n1 = g_norm[e + 1], n2 = g_norm[e + 2], n3 = g_norm[e + 3];
        float4 v0 = hv[s0 * 32 + lane];
        float4 v1 = hv[s1 * 32 + lane];
        float4 v2 = hv[s2 * 32 + lane];
        float4 v3 = hv[s3 * 32 + lane];
        acc.x += n0 * v0.x + n1 * v1.x + n2 * v2.x + n3 * v3.x;
        acc.y += n0 * v0.y + n1 * v1.y + n2 * v2.y + n3 * v3.y;
        acc.z += n0 * v0.z + n1 * v1.z + n2 * v2.z + n3 * v3.z;
        acc.w += n0 * v0.w + n1 * v1.w + n2 * v2.w + n3 * v3.w;
    }
    for (; e < e1; e++) {
        int s = g_srcs[e]; float nm = g_norm[e];
        float4 vv = hv[s * 32 + lane];
        acc.x += nm * vv.x; acc.y += nm * vv.y;
        acc.z += nm * vv.z; acc.w += nm * vv.w;
    }
    float4 b = ((const float4*)bias)[lane];
    acc.x += b.x; acc.y += b.y; acc.z += b.z; acc.w += b.w;
    if (RELU) {
        acc.x = fmaxf(acc.x, 0.f); acc.y = fmaxf(acc.y, 0.f);
        acc.z = fmaxf(acc.z, 0.f); acc.w = fmaxf(acc.w, 0.f);
    }
    ((float4*)out)[gwarp * 32 + lane] = acc;
}

// ---------------- aggregation: one warp per node, 64 features ----------------
template <bool RELU>
__global__ void k_agg64(const float* __restrict__ h,
                        const float* __restrict__ bias,
                        float* __restrict__ out, int n) {
    int gwarp = (blockIdx.x * blockDim.x + threadIdx.x) >> 5;
    if (gwarp >= n) return;
    int lane = threadIdx.x & 31;
    const float2* hv = (const float2*)h;
    float d = g_dis[gwarp];
    float2 v = hv[gwarp * 32 + lane];
    float sn = d * d;
    float2 acc = make_float2(sn * v.x, sn * v.y);
    int e = g_rowptr[gwarp], e1 = g_rowptr[gwarp + 1];
    for (; e + 4 <= e1; e += 4) {
        int s0 = g_srcs[e + 0], s1 = g_srcs[e + 1], s2 = g_srcs[e + 2], s3 = g_srcs[e + 3];
        float n0 = g_norm[e + 0], n1 = g_norm[e + 1], n2 = g_norm[e + 2], n3 = g_norm[e + 3];
        float2 v0 = hv[s0 * 32 + lane];
        float2 v1 = hv[s1 * 32 + lane];
        float2 v2 = hv[s2 * 32 + lane];
        float2 v3 = hv[s3 * 32 + lane];
        acc.x += n0 * v0.x + n1 * v1.x + n2 * v2.x + n3 * v3.x;
        acc.y += n0 * v0.y + n1 * v1.y + n2 * v2.y + n3 * v3.y;
    }
    for (; e < e1; e++) {
        int s = g_srcs[e]; float nm = g_norm[e];
        float2 vv = hv[s * 32 + lane];
        acc.x += nm * vv.x; acc.y += nm * vv.y;
    }
    float2 b = ((const float2*)bias)[lane];
    acc.x += b.x; acc.y += b.y;
    if (RELU) { acc.x = fmaxf(acc.x, 0.f); acc.y = fmaxf(acc.y, 0.f); }
    ((float2*)out)[gwarp * 32 + lane] = acc;
}

// ---------------- launch ----------------
extern "C" void kernel_launch(void* const* d_in, const int* in_sizes, int n_in,
                              void* d_out, int out_size) {
    const float* x    = (const float*)d_in[0];
    const int*   eidx = (const int*)d_in[1];     // int64 in ref -> int32 in harness
    const float* W1   = (const float*)d_in[2];
    const float* b1   = (const float*)d_in[3];
    const float* W2   = (const float*)d_in[4];
    const float* b2   = (const float*)d_in[5];
    float*       out  = (float*)d_out;

    int n = in_sizes[0] / F_IN;          // 50000
    int E = in_sizes[1] / 2;             // 800000
    const int* src = eidx;
    const int* dst = eidx + E;

    const int SMEM = 98304;
    cudaFuncSetAttribute(k_gemm<128>, cudaFuncAttributeMaxDynamicSharedMemorySize, SMEM);
    cudaFuncSetAttribute(k_gemm<64>,  cudaFuncAttributeMaxDynamicSharedMemorySize, SMEM);

    // graph structure build (every call; graph-replay safe)
    k_deg_init<<<(n + 255) / 256, 256>>>(n);
    k_deg_count<<<(E + 255) / 256, 256>>>(dst, E, n);
    k_dis<<<(n + 255) / 256, 256>>>(n);
    k_scan<<<1, 1024>>>(n);
    k_scatter<<<(E + 255) / 256, 256>>>(src, dst, E, n);

    float* h1 = nullptr; cudaGetSymbolAddress((void**)&h1, g_h1);
    float* a1 = nullptr; cudaGetSymbolAddress((void**)&a1, g_a1);
    float* h2 = nullptr; cudaGetSymbolAddress((void**)&h2, g_h2);

    int aggBlocks = (n + 7) / 8;   // 8 warps per 256-thread block, warp per node

    // layer 1
    k_gemm<128><<<(n + 63) / 64, 256, SMEM>>>(x, W1, h1, n);
    k_agg128<true><<<aggBlocks, 256>>>(h1, b1, a1, n);

    // layer 2
    k_gemm<64><<<(n + 127) / 128, 256, SMEM>>>(a1, W2, h2, n);
    k_agg64<false><<<aggBlocks, 256>>>(h2, b2, out, n);
}

// round 4
// speedup vs baseline: 1.1445x; 1.1445x over previous
#include <cuda_runtime.h>
#include <cuda_bf16.h>
#include <math.h>

// ---------------- problem constants ----------------
#define F_IN  128
#define D1    128
#define N_CLS 64
#define MAXN  50000
#define MAXE  800000
#define SCAN_CHUNK 4096            // 1024 threads * 4 elems
#define MAXB ((MAXN + SCAN_CHUNK - 1) / SCAN_CHUNK)

// ---------------- device scratch (no allocations allowed) ----------------
__device__ float g_h1[MAXN * D1];      // x @ W1
__device__ float g_a1[MAXN * D1];      // relu(aggregate(h1) + b1)
__device__ float g_h2[MAXN * N_CLS];   // a1 @ W2
__device__ int   g_deg[MAXN];
__device__ float g_dis[MAXN];
__device__ int   g_rowptr[MAXN + 1];
__device__ int   g_cursor[MAXN];
__device__ int   g_srcs[MAXE];
__device__ float g_norm[MAXE];
__device__ int   g_bsum[MAXB];
__device__ int   g_bcarry[MAXB];

// ---------------- degree ----------------
__global__ void k_deg_init(int n) {
    int i = blockIdx.x * blockDim.x + threadIdx.x;
    if (i < n) g_deg[i] = 1;   // self loop
}

__global__ void k_deg_count(const int* __restrict__ dst, int E, int n) {
    int e = blockIdx.x * blockDim.x + threadIdx.x;
    if (e >= E) return;
    int d = dst[e];
    if ((unsigned)d < (unsigned)n) atomicAdd(&g_deg[d], 1);
}

// ---------------- two-level exclusive scan of (deg-1) ----------------
// pass 1: per-block scan (4096 elems/block), write local exclusives + block sum.
// Also computes dis = rsqrt(deg) (free: deg already in registers).
__global__ void __launch_bounds__(1024) k_scan_blocks(int n) {
    __shared__ int wsum[32];
    int tid = threadIdx.x, lane = tid & 31, wid = tid >> 5;
    int base = blockIdx.x * SCAN_CHUNK + tid * 4;

    int v[4];
    #pragma unroll
    for (int j = 0; j < 4; j++) {
        int i = base + j;
        int dg = (i < n) ? g_deg[i] : 1;
        v[j] = dg - 1;
        if (i < n) g_dis[i] = rsqrtf((float)dg);
    }
    int tsum = v[0] + v[1] + v[2] + v[3];

    // warp inclusive scan of per-thread sums
    int x = tsum;
    #pragma unroll
    for (int off = 1; off < 32; off <<= 1) {
        int y = __shfl_up_sync(0xffffffffu, x, off);
        if (lane >= off) x += y;
    }
    if (lane == 31) wsum[wid] = x;
    __syncthreads();
    if (wid == 0) {
        int w = wsum[lane];
        #pragma unroll
        for (int off = 1; off < 32; off <<= 1) {
            int y = __shfl_up_sync(0xffffffffu, w, off);
            if (lane >= off) w += y;
        }
        wsum[lane] = w;
    }
    __syncthreads();

    int thread_excl = (wid ? wsum[wid - 1] : 0) + (x - tsum);
    int e = thread_excl;
    #pragma unroll
    for (int j = 0; j < 4; j++) {
        int i = base + j;
        if (i < n) g_rowptr[i] = e;
        e += v[j];
    }
    if (tid == 1023) g_bsum[blockIdx.x] = wsum[31];
}

// pass 2: one warp scans the block sums (exclusive), writes rowptr[n]=total
__global__ void k_scan_carry(int nb, int n) {
    int lane = threadIdx.x;
    int v = (lane < nb) ? g_bsum[lane] : 0;
    int x = v;
    #pragma unroll
    for (int off = 1; off < 32; off <<= 1) {
        int y = __shfl_up_sync(0xffffffffu, x, off);
        if (lane >= off) x += y;
    }
    if (lane < nb) g_bcarry[lane] = x - v;
    if (lane == 31) g_rowptr[n] = x;
}

// pass 3: add carries, init cursor
__global__ void k_scan_add(int n) {
    int i = blockIdx.x * blockDim.x + threadIdx.x;
    if (i >= n) return;
    int r = g_rowptr[i] + g_bcarry[i >> 12];   // 4096 = 1<<12
    g_rowptr[i] = r;
    g_cursor[i] = r;
}

// ---------------- scatter edges into dst-sorted CSR ----------------
__global__ void k_scatter(const int* __restrict__ src,
                          const int* __restrict__ dst, int E, int n) {
    int e = blockIdx.x * blockDim.x + threadIdx.x;
    if (e >= E) return;
    int s = src[e];
    int d = dst[e];
    if ((unsigned)s >= (unsigned)n || (unsigned)d >= (unsigned)n) return;
    int pos = atomicAdd(&g_cursor[d], 1);
    g_srcs[pos] = s;
    g_norm[pos] = g_dis[s] * g_dis[d];
}

// ---------------- SIMT fp32 GEMM: C[M,TN] = A[M,128] @ B[128,TN] ----------------
// block = 256 threads; per-thread tile 8 rows x 4 cols
template <int TN>
__global__ void __launch_bounds__(256) k_gemm(const float* __restrict__ A,
                                              const float* __restrict__ B,
                                              float* __restrict__ C, int M) {
    constexpr int K = 128;
    constexpr int TCOLS = TN / 4;            // 32 (TN=128) or 16 (TN=64)
    constexpr int TM = (256 / TCOLS) * 8;    // 64 or 128
    extern __shared__ float sm[];
    float* Ws = sm;            // [K][TN]
    float* Xs = sm + K * TN;   // [TM][K]
    int tid = threadIdx.x;
    int blockRow = blockIdx.x * TM;

    // load B (whole weight) into smem
    {
        const float4* Bv = (const float4*)B;
        float4* Wv = (float4*)Ws;
        for (int i = tid; i < K * TN / 4; i += 256) Wv[i] = Bv[i];
    }
    // load A tile
    {
        float4* Xv = (float4*)Xs;
        for (int i = tid; i < TM * K / 4; i += 256) {
            int r = i >> 5;          // K/4 == 32 float4 per row
            int c = i & 31;
            int row = blockRow + r;
            float4 val = make_float4(0.f, 0.f, 0.f, 0.f);
            if (row < M) val = ((const float4*)A)[row * 32 + c];
            Xv[i] = val;
        }
    }
    __syncthreads();

    int tx = tid % TCOLS, ty = tid / TCOLS;
    int r0 = ty * 8;
    float4 acc[8];
    #pragma unroll
    for (int r = 0; r < 8; r++) acc[r] = make_float4(0.f, 0.f, 0.f, 0.f);

    #pragma unroll 8
    for (int k = 0; k < K; k++) {
        float4 b = *(const float4*)&Ws[k * TN + tx * 4];
        #pragma unroll
        for (int r = 0; r < 8; r++) {
            float a = Xs[(r0 + r) * K + k];
            acc[r].x += a * b.x;
            acc[r].y += a * b.y;
            acc[r].z += a * b.z;
            acc[r].w += a * b.w;
        }
    }
    #pragma unroll
    for (int r = 0; r < 8; r++) {
        int row = blockRow + r0 + r;
        if (row < M) ((float4*)C)[row * (TN / 4) + tx] = acc[r];
    }
}

// ---------------- aggregation: one warp per node, 128 features ----------------
template <bool RELU>
__global__ void k_agg128(const float* __restrict__ h,
                         const float* __restrict__ bias,
                         float* __restrict__ out, int n) {
    int gwarp = (blockIdx.x * blockDim.x + threadIdx.x) >> 5;
    if (gwarp >= n) return;
    int lane = threadIdx.x & 31;
    const float4* hv = (const float4*)h;
    float d = g_dis[gwarp];
    float4 v = hv[gwarp * 32 + lane];
    float sn = d * d;                           // self-loop norm
    float4 acc = make_float4(sn * v.x, sn * v.y, sn * v.z, sn * v.w);
    int e = g_rowptr[gwarp], e1 = g_rowptr[gwarp + 1];
    for (; e + 4 <= e1; e += 4) {
        int s0 = g_srcs[e + 0], s1 = g_srcs[e + 1], s2 = g_srcs[e + 2], s3 = g_srcs[e + 3];
        float n0 = g_norm[e + 0], n1 = g_norm[e + 1], n2 = g_norm[e + 2], n3 = g_norm[e + 3];
        float4 v0 = hv[s0 * 32 + lane];
        float4 v1 = hv[s1 * 32 + lane];
        float4 v2 = hv[s2 * 32 + lane];
        float4 v3 = hv[s3 * 32 + lane];
        acc.x += n0 * v0.x + n1 * v1.x + n2 * v2.x + n3 * v3.x;
        acc.y += n0 * v0.y + n1 * v1.y + n2 * v2.y + n3 * v3.y;
        acc.z += n0 * v0.z + n1 * v1.z + n2 * v2.z + n3 * v3.z;
        acc.w += n0 * v0.w + n1 * v1.w + n2 * v2.w + n3 * v3.w;
    }
    for (; e < e1; e++) {
        int s = g_srcs[e]; float nm = g_norm[e];
        float4 vv = hv[s * 32 + lane];
        acc.x += nm * vv.x; acc.y += nm * vv.y;
        acc.z += nm * vv.z; acc.w += nm * vv.w;
    }
    float4 b = ((const float4*)bias)[lane];
    acc.x += b.x; acc.y += b.y; acc.z += b.z; acc.w += b.w;
    if (RELU) {
        acc.x = fmaxf(acc.x, 0.f); acc.y = fmaxf(acc.y, 0.f);
        acc.z = fmaxf(acc.z, 0.f); acc.w = fmaxf(acc.w, 0.f);
    }
    ((float4*)out)[gwarp * 32 + lane] = acc;
}

// ---------------- aggregation: one warp per node, 64 features ----------------
template <bool RELU>
__global__ void k_agg64(const float* __restrict__ h,
                        const float* __restrict__ bias,
                        float* __restrict__ out, int n) {
    int gwarp = (blockIdx.x * blockDim.x + threadIdx.x) >> 5;
    if (gwarp >= n) return;
    int lane = threadIdx.x & 31;
    const float2* hv = (const float2*)h;
    float d = g_dis[gwarp];
    float2 v = hv[gwarp * 32 + lane];
    float sn = d * d;
    float2 acc = make_float2(sn * v.x, sn * v.y);
    int e = g_rowptr[gwarp], e1 = g_rowptr[gwarp + 1];
    for (; e + 4 <= e1; e += 4) {
        int s0 = g_srcs[e + 0], s1 = g_srcs[e + 1], s2 = g_srcs[e + 2], s3 = g_srcs[e + 3];
        float n0 = g_norm[e + 0], n1 = g_norm[e + 1], n2 = g_norm[e + 2], n3 = g_norm[e + 3];
        float2 v0 = hv[s0 * 32 + lane];
        float2 v1 = hv[s1 * 32 + lane];
        float2 v2 = hv[s2 * 32 + lane];
        float2 v3 = hv[s3 * 32 + lane];
        acc.x += n0 * v0.x + n1 * v1.x + n2 * v2.x + n3 * v3.x;
        acc.y += n0 * v0.y + n1 * v1.y + n2 * v2.y + n3 * v3.y;
    }
    for (; e < e1; e++) {
        int s = g_srcs[e]; float nm = g_norm[e];
        float2 vv = hv[s * 32 + lane];
        acc.x += nm * vv.x; acc.y += nm * vv.y;
    }
    float2 b = ((const float2*)bias)[lane];
    acc.x += b.x; acc.y += b.y;
    if (RELU) { acc.x = fmaxf(acc.x, 0.f); acc.y = fmaxf(acc.y, 0.f); }
    ((float2*)out)[gwarp * 32 + lane] = acc;
}

// ---------------- launch ----------------
extern "C" void kernel_launch(void* const* d_in, const int* in_sizes, int n_in,
                              void* d_out, int out_size) {
    const float* x    = (const float*)d_in[0];
    const int*   eidx = (const int*)d_in[1];     // int64 in ref -> int32 in harness
    const float* W1   = (const float*)d_in[2];
    const float* b1   = (const float*)d_in[3];
    const float* W2   = (const float*)d_in[4];
    const float* b2   = (const float*)d_in[5];
    float*       out  = (float*)d_out;

    int n = in_sizes[0] / F_IN;          // 50000
    int E = in_sizes[1] / 2;             // 800000
    const int* src = eidx;
    const int* dst = eidx + E;
    int nb = (n + SCAN_CHUNK - 1) / SCAN_CHUNK;   // 13

    const int SMEM = 98304;
    cudaFuncSetAttribute(k_gemm<128>, cudaFuncAttributeMaxDynamicSharedMemorySize, SMEM);
    cudaFuncSetAttribute(k_gemm<64>,  cudaFuncAttributeMaxDynamicSharedMemorySize, SMEM);

    // graph structure build (every call; graph-replay safe)
    k_deg_init<<<(n + 255) / 256, 256>>>(n);
    k_deg_count<<<(E + 255) / 256, 256>>>(dst, E, n);
    k_scan_blocks<<<nb, 1024>>>(n);
    k_scan_carry<<<1, 32>>>(nb, n);
    k_scan_add<<<(n + 255) / 256, 256>>>(n);
    k_scatter<<<(E + 255) / 256, 256>>>(src, dst, E, n);

    float* h1 = nullptr; cudaGetSymbolAddress((void**)&h1, g_h1);
    float* a1 = nullptr; cudaGetSymbolAddress((void**)&a1, g_a1);
    float* h2 = nullptr; cudaGetSymbolAddress((void**)&h2, g_h2);

    int aggBlocks = (n + 7) / 8;   // 8 warps per 256-thread block, warp per node

    // layer 1
    k_gemm<128><<<(n + 63) / 64, 256, SMEM>>>(x, W1, h1, n);
    k_agg128<true><<<aggBlocks, 256>>>(h1, b1, a1, n);

    // layer 2
    k_gemm<64><<<(n + 127) / 128, 256, SMEM>>>(a1, W2, h2, n);
    k_agg64<false><<<aggBlocks, 256>>>(h2, b2, out, n);
}